// round 2
// baseline (speedup 1.0000x reference)
#include <cuda_runtime.h>
#include <cuda_bf16.h>

// Fixed problem constants
#define PH 7
#define PW 7
#define SR 2
#define SY (PH*SR)   // 14 sample rows
#define SX (PW*SR)   // 14 sample cols
#define NSAMP (SY*SX) // 196
#define C_CH 256
#define H_FEAT 200
#define W_FEAT 272
#define HW (H_FEAT*W_FEAT)
#define SCALE 0.25f

#define CH_PER_BLOCK 64
#define CHUNKS (C_CH / CH_PER_BLOCK)   // 4
#define NTHREADS 224                   // 7 warps; 196 active in sample phase

__global__ __launch_bounds__(NTHREADS) void roi_align_smem(
    const float* __restrict__ feat,
    const float* __restrict__ rois,
    float* __restrict__ out)
{
    __shared__ int   s_yoff_l[SY], s_yoff_h[SY];
    __shared__ float s_wly[SY], s_why[SY];
    __shared__ int   s_xl[SX], s_xh[SX];
    __shared__ float s_wlx[SX], s_whx[SX];
    __shared__ float s_samp[NSAMP];
    __shared__ int   s_base;

    const int roi = blockIdx.x / CHUNKS;
    const int c0  = (blockIdx.x % CHUNKS) * CH_PER_BLOCK;
    const int t   = threadIdx.x;

    // ---- per-ROI precompute (28 threads) ----
    if (t < SY + SX) {
        const float* r = rois + roi * 5;
        float sw = r[1] * SCALE, sh = r[2] * SCALE;
        float ew = r[3] * SCALE, eh = r[4] * SCALE;
        float bin_w = fmaxf(ew - sw, 1.0f) / PW;
        float bin_h = fmaxf(eh - sh, 1.0f) / PH;
        if (t < SY) {
            float y = sh + ((float)t + 0.5f) * 0.5f * bin_h;
            float v = (y > -1.0f && y < (float)H_FEAT) ? 1.0f : 0.0f;
            float yc = fminf(fmaxf(y, 0.0f), (float)(H_FEAT - 1));
            int   yl = (int)floorf(yc);
            int   yh = min(yl + 1, H_FEAT - 1);
            float ly = yc - (float)yl;
            s_yoff_l[t] = yl * W_FEAT;
            s_yoff_h[t] = yh * W_FEAT;
            s_wly[t] = ly * v;
            s_why[t] = (1.0f - ly) * v;
        } else {
            int   sx = t - SY;
            float x = sw + ((float)sx + 0.5f) * 0.5f * bin_w;
            float v = (x > -1.0f && x < (float)W_FEAT) ? 1.0f : 0.0f;
            float xc = fminf(fmaxf(x, 0.0f), (float)(W_FEAT - 1));
            int   xl = (int)floorf(xc);
            int   xh = min(xl + 1, W_FEAT - 1);
            float lx = xc - (float)xl;
            s_xl[sx] = xl;
            s_xh[sx] = xh;
            s_wlx[sx] = lx * v;
            s_whx[sx] = (1.0f - lx) * v;
        }
    }
    if (t == 0) {
        s_base = ((int)rois[roi * 5] * C_CH + c0) * HW;
    }
    __syncthreads();

    // ---- hoist loop-invariant per-thread state into registers ----
    // Sample-phase threads (t < 196)
    int   ol = 0, oh = 0, xl = 0, xh = 0;
    float wly = 0.f, why = 0.f, wlx = 0.f, whx = 0.f;
    if (t < NSAMP) {
        int sy = t / SX, sx = t % SX;
        ol  = s_yoff_l[sy];
        oh  = s_yoff_h[sy];
        xl  = s_xl[sx];
        xh  = s_xh[sx];
        wly = s_wly[sy];
        why = s_why[sy];
        wlx = s_wlx[sx];
        whx = s_whx[sx];
    }
    // Reduce-phase threads (t < 49)
    int b0 = 0, obase = 0;
    if (t < PH * PW) {
        int ph = t / PW, pw = t % PW;
        b0 = (2 * ph) * SX + 2 * pw;
        obase = (roi * C_CH + c0) * (PH * PW) + t;
    }
    const int fbase = s_base;

    for (int ch = 0; ch < CH_PER_BLOCK; ch++) {
        const float* f = feat + fbase + ch * HW;
        if (t < NSAMP) {
            float v00 = __ldg(f + ol + xl);
            float v01 = __ldg(f + ol + xh);
            float v10 = __ldg(f + oh + xl);
            float v11 = __ldg(f + oh + xh);
            float r0 = whx * v00 + wlx * v01;
            float r1 = whx * v10 + wlx * v11;
            s_samp[t] = why * r0 + wly * r1;
        }
        __syncthreads();
        if (t < PH * PW) {
            float s = s_samp[b0] + s_samp[b0 + 1]
                    + s_samp[b0 + SX] + s_samp[b0 + SX + 1];
            out[obase + ch * (PH * PW)] = 0.25f * s;
        }
        __syncthreads();
    }
}

extern "C" void kernel_launch(void* const* d_in, const int* in_sizes, int n_in,
                              void* d_out, int out_size) {
    const float* feat = (const float*)d_in[0];
    const float* rois = (const float*)d_in[1];
    float* out = (float*)d_out;

    int n_rois = in_sizes[1] / 5;
    int blocks = n_rois * CHUNKS;
    roi_align_smem<<<blocks, NTHREADS>>>(feat, rois, out);
}

// round 4
// speedup vs baseline: 1.4683x; 1.4683x over previous
#include <cuda_runtime.h>
#include <cuda_bf16.h>

// Fixed problem constants
#define PH 7
#define PW 7
#define C_CH 256
#define H_FEAT 200
#define W_FEAT 272
#define HW (H_FEAT*W_FEAT)
#define SCALE 0.25f

#define CH_PER_BLOCK 16
#define CHUNKS (C_CH / CH_PER_BLOCK)   // 16
#define NTHREADS 224                   // 7 warps = 7 bin rows

__global__ __launch_bounds__(NTHREADS) void roi_align_warp(
    const float* __restrict__ feat,
    const float* __restrict__ rois,
    float* __restrict__ out,
    int n_rois)
{
    // Block -> (channel chunk, roi). Consecutive blocks share the chunk so a
    // scheduling wave works on one 7MB channel slice -> L2 reuse across rois.
    const int roi   = blockIdx.x % n_rois;
    const int chunk = blockIdx.x / n_rois;
    const int c0    = chunk * CH_PER_BLOCK;

    const int t    = threadIdx.x;
    const int wid  = t >> 5;          // bin row 0..6
    const int lane = t & 31;
    const int half = lane >> 4;       // 0 or 1: which sample row of the bin row
    const int sx   = lane & 15;       // sample col 0..13 (14,15 idle)
    const int sy   = wid * 2 + half;  // sample row 0..13

    const bool active = (sx < 14);

    // ---- per-ROI setup (registers, once) ----
    const float* r = rois + roi * 5;
    const int   b  = (int)r[0];
    const float swc = r[1] * SCALE;
    const float shc = r[2] * SCALE;
    const float ewc = r[3] * SCALE;
    const float ehc = r[4] * SCALE;
    const float bin_w = fmaxf(ewc - swc, 1.0f) / PW;
    const float bin_h = fmaxf(ehc - shc, 1.0f) / PH;

    // y sample
    float y  = shc + ((float)sy + 0.5f) * 0.5f * bin_h;
    float vy = (y > -1.0f && y < (float)H_FEAT) ? 1.0f : 0.0f;
    float yc = fminf(fmaxf(y, 0.0f), (float)(H_FEAT - 1));
    int   yl = (int)floorf(yc);
    int   yh = min(yl + 1, H_FEAT - 1);
    float ly = yc - (float)yl;
    float wly = ly * vy;
    float why = (1.0f - ly) * vy;
    int ol = yl * W_FEAT;
    int oh = yh * W_FEAT;

    // x sample
    float x  = swc + ((float)sx + 0.5f) * 0.5f * bin_w;
    float vx = (x > -1.0f && x < (float)W_FEAT) ? 1.0f : 0.0f;
    float xc = fminf(fmaxf(x, 0.0f), (float)(W_FEAT - 1));
    int   xl = (int)floorf(xc);
    int   xh = min(xl + 1, W_FEAT - 1);
    float lx = xc - (float)xl;
    float wlx = lx * vx;
    float whx = (1.0f - lx) * vx;

    if (!active) {  // idle lanes: harmless loads, zero contribution
        xl = 0; xh = 0; ol = 0; oh = 0;
        wlx = 0.0f; whx = 0.0f; wly = 0.0f; why = 0.0f;
    }

    const float* f0 = feat + ((long)b * C_CH + c0) * HW;

    const bool writer = active && ((lane & 1) == 0) && half == 0;
    // 7 writer lanes (0,2,...,12) -> 7 consecutive outputs of this bin row
    const long obase = ((long)roi * C_CH + c0) * (PH * PW) + wid * PW + (sx >> 1);

    #pragma unroll
    for (int ch = 0; ch < CH_PER_BLOCK; ch++) {
        const float* f = f0 + ch * HW;
        float v00 = __ldg(f + ol + xl);
        float v01 = __ldg(f + ol + xh);
        float v10 = __ldg(f + oh + xl);
        float v11 = __ldg(f + oh + xh);
        float row0 = whx * v00 + wlx * v01;
        float row1 = whx * v10 + wlx * v11;
        float v = why * row0 + wly * row1;
        // 2x2 sample average within the bin
        v += __shfl_xor_sync(0xffffffffu, v, 1);   // combine sx pair
        v += __shfl_xor_sync(0xffffffffu, v, 16);  // combine sy pair
        if (writer) out[obase + ch * (PH * PW)] = 0.25f * v;
    }
}

extern "C" void kernel_launch(void* const* d_in, const int* in_sizes, int n_in,
                              void* d_out, int out_size) {
    const float* feat = (const float*)d_in[0];
    const float* rois = (const float*)d_in[1];
    float* out = (float*)d_out;

    int n_rois = in_sizes[1] / 5;
    int blocks = n_rois * CHUNKS;
    roi_align_warp<<<blocks, NTHREADS>>>(feat, rois, out, n_rois);
}